// round 3
// baseline (speedup 1.0000x reference)
#include <cuda_runtime.h>
#include <math.h>
#include <stdint.h>
#include <mma.h>

using namespace nvcuda;

#define NN   50000
#define EE   600000
#define DD   128
#define CC   128
#define GG   64
#define NCLS 10
#define NCAT 512

// ---------------- scratch (static device globals; no allocation) ----------------
__device__ __align__(16) float g_q[NN * CC];
__device__ __align__(16) float g_k[NN * CC];
__device__ __align__(16) float g_v[NN * CC];
__device__ __align__(16) float g_h0[NN * CC];   // layer-0 output (pre-relu)
__device__ __align__(16) float g_h1[NN * CC];   // layer-1 output (pre-relu)
__device__ __align__(16) float g_wh[DD * NCAT]; // tf32-rounded hi part of [Wq|Wk|Wv|Ws]
__device__ __align__(16) float g_wl[DD * NCAT]; // tf32 lo residual
__device__ __align__(16) float g_bcat[NCAT];
__device__ float g_score[EE];
__device__ float g_m[NN];
__device__ float g_den[NN];
__device__ __align__(16) float g_sums[GG * CC];
__device__ float g_cnt[GG];

// ---------------- helpers ----------------
__device__ __forceinline__ void atomicMaxF(float* addr, float val) {
    int old = __float_as_int(*addr);
    while (__int_as_float(old) < val) {
        int assumed = old;
        old = atomicCAS((int*)addr, assumed, __float_as_int(val));
        if (old == assumed) break;
    }
}

__device__ __forceinline__ void red_add_v4(float* addr, float a, float b, float c, float d) {
    asm volatile("red.global.add.v4.f32 [%0], {%1, %2, %3, %4};"
                 :: "l"(addr), "f"(a), "f"(b), "f"(c), "f"(d) : "memory");
}

// ---------------- init kernels ----------------
__global__ void init_nodes_kernel() {
    int i = blockIdx.x * blockDim.x + threadIdx.x;
    if (i < NN) { g_m[i] = -INFINITY; g_den[i] = 0.0f; }
}

__global__ void init_pool_kernel() {
    int i = blockIdx.x * blockDim.x + threadIdx.x;
    if (i < GG * CC) g_sums[i] = 0.0f;
    if (i < GG) g_cnt[i] = 0.0f;
}

// ---------------- weight prep: concat + tf32 hi/lo split ----------------
__global__ void prep_w_kernel(const float* __restrict__ Wq, const float* __restrict__ Wk,
                              const float* __restrict__ Wv, const float* __restrict__ Ws,
                              const float* __restrict__ bq, const float* __restrict__ bk,
                              const float* __restrict__ bv, const float* __restrict__ bs)
{
    int i = blockIdx.x * 256 + threadIdx.x;
    if (i < DD * NCAT) {
        int k = i >> 9, nc = i & (NCAT - 1);
        int o = nc >> 7, n = nc & 127;
        const float* W = (o == 0) ? Wq : (o == 1) ? Wk : (o == 2) ? Wv : Ws;
        float w = W[k * CC + n];
        float hi = wmma::__float_to_tf32(w);
        float lo = wmma::__float_to_tf32(w - hi);
        g_wh[i] = hi;
        g_wl[i] = lo;
    }
    if (i < NCAT) {
        int o = i >> 7, n = i & 127;
        const float* B = (o == 0) ? bq : (o == 1) ? bk : (o == 2) ? bv : bs;
        g_bcat[i] = B[n];
    }
}

// ---------------- wmma tf32 GEMM: Y[:, o*128:+128] = act(X) @ (Wh+Wl) + b ----------------
// grid (391, 4), 256 threads. blockIdx.y = output slab o.
// dynamic smem layout (floats):
//   sA   [128][36]   @ 0        (18432 B)
//   sBh  [32][132]   @ 4608     (16896 B)
//   sBl  [32][132]   @ 8832     (16896 B)
//   sBias[16][132]   @ 13056    (8448 B)
//   epilogue buffer [128][132] overlaps from 0 (after sync)
#define SM_FLOATS (128 * 132)
#define SM_BYTES  (SM_FLOATS * 4)

__global__ __launch_bounds__(256) void gemm_wmma_kernel(
    const float* __restrict__ X,   // null => relu(g_h0)
    int layer)
{
    extern __shared__ float sm[];
    float* sA   = sm;               // ld 36
    float* sBh  = sm + 128 * 36;    // ld 132
    float* sBl  = sBh + 32 * 132;   // ld 132
    float* sBias= sBl + 32 * 132;   // ld 132

    const int tid = threadIdx.x;
    const int w   = tid >> 5;
    const int wr  = w >> 1;         // 0..3 : M offset wr*32
    const int wc  = w & 1;          // 0..1 : N offset wc*64
    const int o   = blockIdx.y;
    const int row0 = blockIdx.x * 128;
    const int nval = min(128, NN - row0);
    const bool relu = (X == nullptr);
    const float* Xp = relu ? g_h0 : X;

    float* O = (o == 0) ? g_q : (o == 1) ? g_k : (o == 2) ? g_v
             : ((layer == 0) ? g_h0 : g_h1);

    // bias tile: 16 identical rows of this slab's 128 biases
    for (int i = tid; i < 16 * 128; i += 256) {
        int r = i >> 7, c = i & 127;
        sBias[r * 132 + c] = g_bcat[o * 128 + c];
    }
    __syncthreads();

    wmma::fragment<wmma::accumulator, 16, 16, 8, float> acc[2][4];
    #pragma unroll
    for (int i = 0; i < 2; i++)
        #pragma unroll
        for (int j = 0; j < 4; j++)
            wmma::load_matrix_sync(acc[i][j], &sBias[wc * 64 + j * 16], 132, wmma::mem_row_major);

    for (int k0 = 0; k0 < DD; k0 += 32) {
        __syncthreads();
        // A chunk: rows 0..127, cols k0..k0+31 (relu + bounds)
        #pragma unroll
        for (int i = tid; i < 1024; i += 256) {
            int r = i >> 3, c4 = i & 7;
            float4 v = make_float4(0.f, 0.f, 0.f, 0.f);
            if (r < nval)
                v = reinterpret_cast<const float4*>(Xp)[(size_t)(row0 + r) * 32 + (k0 >> 2) + c4];
            if (relu) {
                v.x = fmaxf(v.x, 0.f); v.y = fmaxf(v.y, 0.f);
                v.z = fmaxf(v.z, 0.f); v.w = fmaxf(v.w, 0.f);
            }
            *reinterpret_cast<float4*>(&sA[r * 36 + c4 * 4]) = v;
        }
        // B chunks (hi + lo): rows k0..k0+31, cols o*128..+128
        #pragma unroll
        for (int i = tid; i < 1024; i += 256) {
            int r = i >> 5, c4 = i & 31;
            size_t gi = (size_t)(k0 + r) * NCAT + o * 128 + c4 * 4;
            *reinterpret_cast<float4*>(&sBh[r * 132 + c4 * 4]) =
                *reinterpret_cast<const float4*>(&g_wh[gi]);
            *reinterpret_cast<float4*>(&sBl[r * 132 + c4 * 4]) =
                *reinterpret_cast<const float4*>(&g_wl[gi]);
        }
        __syncthreads();

        #pragma unroll
        for (int kk = 0; kk < 32; kk += 8) {
            wmma::fragment<wmma::matrix_a, 16, 16, 8, wmma::precision::tf32, wmma::row_major> af[2];
            #pragma unroll
            for (int i = 0; i < 2; i++) {
                wmma::load_matrix_sync(af[i], &sA[(wr * 32 + i * 16) * 36 + kk], 36);
                #pragma unroll
                for (int t = 0; t < af[i].num_elements; t++)
                    af[i].x[t] = wmma::__float_to_tf32(af[i].x[t]);
            }
            #pragma unroll
            for (int j = 0; j < 4; j++) {
                wmma::fragment<wmma::matrix_b, 16, 16, 8, wmma::precision::tf32, wmma::row_major> bh, bl;
                wmma::load_matrix_sync(bh, &sBh[kk * 132 + wc * 64 + j * 16], 132);
                wmma::load_matrix_sync(bl, &sBl[kk * 132 + wc * 64 + j * 16], 132);
                #pragma unroll
                for (int i = 0; i < 2; i++) {
                    wmma::mma_sync(acc[i][j], af[i], bh, acc[i][j]);
                    wmma::mma_sync(acc[i][j], af[i], bl, acc[i][j]);
                }
            }
        }
    }

    if (nval == 128) {
        // fast path: direct global stores
        #pragma unroll
        for (int i = 0; i < 2; i++)
            #pragma unroll
            for (int j = 0; j < 4; j++)
                wmma::store_matrix_sync(
                    O + (size_t)(row0 + wr * 32 + i * 16) * CC + wc * 64 + j * 16,
                    acc[i][j], CC, wmma::mem_row_major);
    } else {
        // slow path (last CTA): stage in smem, guarded copy
        __syncthreads();
        #pragma unroll
        for (int i = 0; i < 2; i++)
            #pragma unroll
            for (int j = 0; j < 4; j++)
                wmma::store_matrix_sync(
                    &sm[(wr * 32 + i * 16) * 132 + wc * 64 + j * 16],
                    acc[i][j], 132, wmma::mem_row_major);
        __syncthreads();
        for (int i = tid; i < 128 * 32; i += 256) {
            int r = i >> 5, c4 = i & 31;
            if (r < nval) {
                float4 v;
                v.x = sm[r * 132 + c4 * 4 + 0];
                v.y = sm[r * 132 + c4 * 4 + 1];
                v.z = sm[r * 132 + c4 * 4 + 2];
                v.w = sm[r * 132 + c4 * 4 + 3];
                *reinterpret_cast<float4*>(&O[(size_t)(row0 + r) * CC + c4 * 4]) = v;
            }
        }
    }
}

// ---------------- edge pass 1: score + segment max ----------------
__global__ __launch_bounds__(256) void edge_score_kernel(
    const int* __restrict__ src, const int* __restrict__ dst)
{
    int t = blockIdx.x * 256 + threadIdx.x;
    int e = t >> 5;
    int lane = t & 31;
    if (e >= EE) return;
    int s = src[e], d = dst[e];
    float4 qa = reinterpret_cast<const float4*>(g_q)[d * 32 + lane];
    float4 ka = reinterpret_cast<const float4*>(g_k)[s * 32 + lane];
    float dot = qa.x * ka.x + qa.y * ka.y + qa.z * ka.z + qa.w * ka.w;
    #pragma unroll
    for (int o = 16; o > 0; o >>= 1) dot += __shfl_xor_sync(0xffffffffu, dot, o);
    if (lane == 0) {
        float sc = dot * 0.08838834764831843f;   // 1/sqrt(128)
        g_score[e] = sc;
        atomicMaxF(&g_m[d], sc);
    }
}

// ---------------- edge pass 2: exp + denominator ----------------
__global__ __launch_bounds__(256) void edge_exp_kernel(const int* __restrict__ dst)
{
    int e = blockIdx.x * 256 + threadIdx.x;
    if (e >= EE) return;
    int d = dst[e];
    float w = expf(g_score[e] - g_m[d]);
    g_score[e] = w;
    atomicAdd(&g_den[d], w);
}

// ---------------- edge pass 3: alpha * v scatter ----------------
__global__ __launch_bounds__(256) void edge_scatter_kernel(
    const int* __restrict__ src, const int* __restrict__ dst, int layer)
{
    int t = blockIdx.x * 256 + threadIdx.x;
    int e = t >> 5;
    int lane = t & 31;
    if (e >= EE) return;
    int s = src[e], d = dst[e];
    float alpha = g_score[e] / g_den[d];
    float4 vv = reinterpret_cast<const float4*>(g_v)[s * 32 + lane];
    float* O = (layer == 0) ? g_h0 : g_h1;
    red_add_v4(&O[d * CC + lane * 4],
               alpha * vv.x, alpha * vv.y, alpha * vv.z, alpha * vv.w);
}

// ---------------- global mean pool (reads relu(g_h1)) ----------------
__global__ __launch_bounds__(256) void pool_kernel(const int* __restrict__ batch)
{
    int t = blockIdx.x * 256 + threadIdx.x;
    int n = t >> 5;
    int lane = t & 31;
    if (n >= NN) return;
    int g = batch[n];
    float4 h = reinterpret_cast<const float4*>(g_h1)[n * 32 + lane];
    h.x = fmaxf(h.x, 0.f); h.y = fmaxf(h.y, 0.f);
    h.z = fmaxf(h.z, 0.f); h.w = fmaxf(h.w, 0.f);
    red_add_v4(&g_sums[g * CC + lane * 4], h.x, h.y, h.z, h.w);
    if (lane == 0) atomicAdd(&g_cnt[g], 1.0f);
}

// ---------------- classifier + log_softmax ----------------
__global__ void final_kernel(const float* __restrict__ W_fc,
                             const float* __restrict__ b_fc,
                             float* __restrict__ out)
{
    int g = blockIdx.x;
    int j = threadIdx.x;
    __shared__ float sl[12];
    float inv = 1.0f / fmaxf(g_cnt[g], 1.0f);
    if (j < NCLS) {
        float acc = b_fc[j];
        for (int c = 0; c < CC; c++)
            acc += g_sums[g * CC + c] * inv * W_fc[c * NCLS + j];
        sl[j] = acc;
    }
    __syncwarp();
    if (j == 0) {
        float mx = sl[0];
        for (int i = 1; i < NCLS; i++) mx = fmaxf(mx, sl[i]);
        float ssum = 0.f;
        for (int i = 0; i < NCLS; i++) ssum += expf(sl[i] - mx);
        sl[10] = mx + logf(ssum);
    }
    __syncwarp();
    if (j < NCLS) out[g * NCLS + j] = sl[j] - sl[10];
}

// ---------------- launch ----------------
extern "C" void kernel_launch(void* const* d_in, const int* in_sizes, int n_in,
                              void* d_out, int out_size)
{
    const float* x    = (const float*)d_in[0];
    const int*   ei   = (const int*)d_in[1];
    const int*   batch= (const int*)d_in[2];
    const float* Wq   = (const float*)d_in[3];
    const float* bq   = (const float*)d_in[4];
    const float* Wk   = (const float*)d_in[5];
    const float* bk   = (const float*)d_in[6];
    const float* Wv   = (const float*)d_in[7];
    const float* bv   = (const float*)d_in[8];
    const float* Ws   = (const float*)d_in[9];
    const float* bs   = (const float*)d_in[10];
    const float* W_fc = (const float*)d_in[11];
    const float* b_fc = (const float*)d_in[12];
    float* out = (float*)d_out;

    const int* src = ei;
    const int* dst = ei + EE;

    static int smem_set = 0;
    if (!smem_set) {
        cudaFuncSetAttribute(gemm_wmma_kernel,
                             cudaFuncAttributeMaxDynamicSharedMemorySize, SM_BYTES);
        smem_set = 1;
    }

    const int gemm_gx   = (NN + 127) / 128;          // 391
    const int edge_gx   = (EE * 32 + 255) / 256;     // 75000
    const int edge1_gx  = (EE + 255) / 256;          // 2344
    const int node_gx   = (NN + 255) / 256;          // 196
    const int pool_gx   = (NN * 32 + 255) / 256;     // 6250
    const int prep_gx   = (DD * NCAT + 255) / 256;   // 256

    init_pool_kernel<<<(GG * CC + 255) / 256, 256>>>();

    for (int l = 0; l < 2; l++) {
        init_nodes_kernel<<<node_gx, 256>>>();
        prep_w_kernel<<<prep_gx, 256>>>(
            Wq + l * DD * CC, Wk + l * DD * CC, Wv + l * DD * CC, Ws + l * DD * CC,
            bq + l * CC, bk + l * CC, bv + l * CC, bs + l * CC);
        gemm_wmma_kernel<<<dim3(gemm_gx, 4), 256, SM_BYTES>>>(
            (l == 0) ? x : nullptr, l);
        edge_score_kernel<<<edge_gx, 256>>>(src, dst);
        edge_exp_kernel<<<edge1_gx, 256>>>(dst);
        edge_scatter_kernel<<<edge_gx, 256>>>(src, dst, l);
    }

    pool_kernel<<<pool_gx, 256>>>(batch);
    final_kernel<<<GG, 32>>>(W_fc, b_fc, out);
}

// round 4
// speedup vs baseline: 1.3255x; 1.3255x over previous
#include <cuda_runtime.h>
#include <math.h>
#include <stdint.h>
#include <mma.h>

using namespace nvcuda;

#define NN     50000
#define NN_PAD 50048          // 391 * 128, so every GEMM CTA stores unguarded
#define EE     600000
#define DD     128
#define CC     128
#define GG     64
#define NCLS   10
#define NCAT   512

// ---------------- scratch (static device globals; no allocation) ----------------
__device__ __align__(16) float g_q[NN_PAD * CC];
__device__ __align__(16) float g_k[NN_PAD * CC];
__device__ __align__(16) float g_v[NN_PAD * CC];
__device__ __align__(16) float g_h0[NN_PAD * CC];   // layer-0 output (pre-relu)
__device__ __align__(16) float g_h1[NN_PAD * CC];   // layer-1 output (pre-relu)
__device__ __align__(16) float g_wh[DD * NCAT];     // tf32-rounded [Wq|Wk|Wv|Ws]
__device__ __align__(16) float g_bcat[NCAT];
__device__ float g_score[EE];
__device__ float g_m[NN];
__device__ float g_den[NN];
__device__ __align__(16) float g_sums[GG * CC];
__device__ float g_cnt[GG];

// ---------------- helpers ----------------
__device__ __forceinline__ void atomicMaxF(float* addr, float val) {
    int old = __float_as_int(*addr);
    while (__int_as_float(old) < val) {
        int assumed = old;
        old = atomicCAS((int*)addr, assumed, __float_as_int(val));
        if (old == assumed) break;
    }
}

__device__ __forceinline__ void red_add_v4(float* addr, float a, float b, float c, float d) {
    asm volatile("red.global.add.v4.f32 [%0], {%1, %2, %3, %4};"
                 :: "l"(addr), "f"(a), "f"(b), "f"(c), "f"(d) : "memory");
}

// ---------------- init kernels ----------------
__global__ void init_nodes_kernel() {
    int i = blockIdx.x * blockDim.x + threadIdx.x;
    if (i < NN) { g_m[i] = -INFINITY; g_den[i] = 0.0f; }
}

__global__ void init_pool_kernel() {
    int i = blockIdx.x * blockDim.x + threadIdx.x;
    if (i < GG * CC) g_sums[i] = 0.0f;
    if (i < GG) g_cnt[i] = 0.0f;
}

// ---------------- weight prep: concat + tf32 round ----------------
__global__ void prep_w_kernel(const float* __restrict__ Wq, const float* __restrict__ Wk,
                              const float* __restrict__ Wv, const float* __restrict__ Ws,
                              const float* __restrict__ bq, const float* __restrict__ bk,
                              const float* __restrict__ bv, const float* __restrict__ bs)
{
    int i = blockIdx.x * 256 + threadIdx.x;
    if (i < DD * NCAT) {
        int k = i >> 9, nc = i & (NCAT - 1);
        int o = nc >> 7, n = nc & 127;
        const float* W = (o == 0) ? Wq : (o == 1) ? Wk : (o == 2) ? Wv : Ws;
        g_wh[i] = wmma::__float_to_tf32(W[k * CC + n]);
    }
    if (i < NCAT) {
        int o = i >> 7, n = i & 127;
        const float* B = (o == 0) ? bq : (o == 1) ? bk : (o == 2) ? bv : bs;
        g_bcat[i] = B[n];
    }
}

// ---------------- wmma tf32 GEMM: Y[:, o*128:+128] = act(X) @ W + b ----------------
// grid (391, 4), 256 threads, static smem 43.8 KB, <=128 regs (2 CTAs/SM min).
__global__ __launch_bounds__(256, 2) void gemm_wmma_kernel(
    const float* __restrict__ X,   // null => relu(g_h0)
    int layer)
{
    __shared__ float sA[128 * 36];
    __shared__ float sB[32 * 132];
    __shared__ float sBias[16 * 132];

    const int tid = threadIdx.x;
    const int w   = tid >> 5;
    const int wr  = w >> 1;         // 0..3 : M offset wr*32
    const int wc  = w & 1;          // 0..1 : N offset wc*64
    const int o   = blockIdx.y;
    const int row0 = blockIdx.x * 128;
    const bool relu = (X == nullptr);
    const float* Xp = relu ? g_h0 : X;

    float* O = (o == 0) ? g_q : (o == 1) ? g_k : (o == 2) ? g_v
             : ((layer == 0) ? g_h0 : g_h1);

    // bias tile: 16 identical rows of this slab's 128 biases
    for (int i = tid; i < 16 * 128; i += 256) {
        int r = i >> 7, c = i & 127;
        sBias[r * 132 + c] = g_bcat[o * 128 + c];
    }
    __syncthreads();

    wmma::fragment<wmma::accumulator, 16, 16, 8, float> acc[2][4];
    #pragma unroll
    for (int i = 0; i < 2; i++)
        #pragma unroll
        for (int j = 0; j < 4; j++)
            wmma::load_matrix_sync(acc[i][j], &sBias[wc * 64 + j * 16], 132, wmma::mem_row_major);

    for (int k0 = 0; k0 < DD; k0 += 32) {
        __syncthreads();
        // A chunk: rows 0..127, cols k0..k0+31 (relu + bounds + tf32 round here)
        #pragma unroll
        for (int i = tid; i < 1024; i += 256) {
            int r = i >> 3, c4 = i & 7;
            float4 v = make_float4(0.f, 0.f, 0.f, 0.f);
            if (row0 + r < NN)
                v = reinterpret_cast<const float4*>(Xp)[(size_t)(row0 + r) * 32 + (k0 >> 2) + c4];
            if (relu) {
                v.x = fmaxf(v.x, 0.f); v.y = fmaxf(v.y, 0.f);
                v.z = fmaxf(v.z, 0.f); v.w = fmaxf(v.w, 0.f);
            }
            v.x = wmma::__float_to_tf32(v.x);
            v.y = wmma::__float_to_tf32(v.y);
            v.z = wmma::__float_to_tf32(v.z);
            v.w = wmma::__float_to_tf32(v.w);
            *reinterpret_cast<float4*>(&sA[r * 36 + c4 * 4]) = v;
        }
        // B chunk: rows k0..k0+31, cols o*128..+128 (already tf32)
        #pragma unroll
        for (int i = tid; i < 1024; i += 256) {
            int r = i >> 5, c4 = i & 31;
            *reinterpret_cast<float4*>(&sB[r * 132 + c4 * 4]) =
                *reinterpret_cast<const float4*>(&g_wh[(size_t)(k0 + r) * NCAT + o * 128 + c4 * 4]);
        }
        __syncthreads();

        #pragma unroll
        for (int kk = 0; kk < 32; kk += 8) {
            wmma::fragment<wmma::matrix_b, 16, 16, 8, wmma::precision::tf32, wmma::row_major> bf[4];
            #pragma unroll
            for (int j = 0; j < 4; j++)
                wmma::load_matrix_sync(bf[j], &sB[kk * 132 + wc * 64 + j * 16], 132);
            #pragma unroll
            for (int i = 0; i < 2; i++) {
                wmma::fragment<wmma::matrix_a, 16, 16, 8, wmma::precision::tf32, wmma::row_major> af;
                wmma::load_matrix_sync(af, &sA[(wr * 32 + i * 16) * 36 + kk], 36);
                #pragma unroll
                for (int j = 0; j < 4; j++)
                    wmma::mma_sync(acc[i][j], af, bf[j], acc[i][j]);
            }
        }
    }

    // direct store (buffers padded to NN_PAD rows; rows >= NN are scratch)
    #pragma unroll
    for (int i = 0; i < 2; i++)
        #pragma unroll
        for (int j = 0; j < 4; j++)
            wmma::store_matrix_sync(
                O + (size_t)(row0 + wr * 32 + i * 16) * CC + wc * 64 + j * 16,
                acc[i][j], CC, wmma::mem_row_major);
}

// ---------------- edge pass 1: score + segment max ----------------
__global__ __launch_bounds__(256) void edge_score_kernel(
    const int* __restrict__ src, const int* __restrict__ dst)
{
    int t = blockIdx.x * 256 + threadIdx.x;
    int e = t >> 5;
    int lane = t & 31;
    if (e >= EE) return;
    int s = src[e], d = dst[e];
    float4 qa = reinterpret_cast<const float4*>(g_q)[d * 32 + lane];
    float4 ka = reinterpret_cast<const float4*>(g_k)[s * 32 + lane];
    float dot = qa.x * ka.x + qa.y * ka.y + qa.z * ka.z + qa.w * ka.w;
    #pragma unroll
    for (int o = 16; o > 0; o >>= 1) dot += __shfl_xor_sync(0xffffffffu, dot, o);
    if (lane == 0) {
        float sc = dot * 0.08838834764831843f;   // 1/sqrt(128)
        g_score[e] = sc;
        atomicMaxF(&g_m[d], sc);
    }
}

// ---------------- edge pass 2: exp + denominator ----------------
__global__ __launch_bounds__(256) void edge_exp_kernel(const int* __restrict__ dst)
{
    int e = blockIdx.x * 256 + threadIdx.x;
    if (e >= EE) return;
    int d = dst[e];
    float w = expf(g_score[e] - g_m[d]);
    g_score[e] = w;
    atomicAdd(&g_den[d], w);
}

// ---------------- edge pass 3: alpha * v scatter ----------------
__global__ __launch_bounds__(256) void edge_scatter_kernel(
    const int* __restrict__ src, const int* __restrict__ dst, int layer)
{
    int t = blockIdx.x * 256 + threadIdx.x;
    int e = t >> 5;
    int lane = t & 31;
    if (e >= EE) return;
    int s = src[e], d = dst[e];
    float alpha = g_score[e] / g_den[d];
    float4 vv = reinterpret_cast<const float4*>(g_v)[s * 32 + lane];
    float* O = (layer == 0) ? g_h0 : g_h1;
    red_add_v4(&O[d * CC + lane * 4],
               alpha * vv.x, alpha * vv.y, alpha * vv.z, alpha * vv.w);
}

// ---------------- global mean pool (reads relu(g_h1)) ----------------
__global__ __launch_bounds__(256) void pool_kernel(const int* __restrict__ batch)
{
    int t = blockIdx.x * 256 + threadIdx.x;
    int n = t >> 5;
    int lane = t & 31;
    if (n >= NN) return;
    int g = batch[n];
    float4 h = reinterpret_cast<const float4*>(g_h1)[n * 32 + lane];
    h.x = fmaxf(h.x, 0.f); h.y = fmaxf(h.y, 0.f);
    h.z = fmaxf(h.z, 0.f); h.w = fmaxf(h.w, 0.f);
    red_add_v4(&g_sums[g * CC + lane * 4], h.x, h.y, h.z, h.w);
    if (lane == 0) atomicAdd(&g_cnt[g], 1.0f);
}

// ---------------- classifier + log_softmax ----------------
__global__ void final_kernel(const float* __restrict__ W_fc,
                             const float* __restrict__ b_fc,
                             float* __restrict__ out)
{
    int g = blockIdx.x;
    int j = threadIdx.x;
    __shared__ float sl[12];
    float inv = 1.0f / fmaxf(g_cnt[g], 1.0f);
    if (j < NCLS) {
        float acc = b_fc[j];
        for (int c = 0; c < CC; c++)
            acc += g_sums[g * CC + c] * inv * W_fc[c * NCLS + j];
        sl[j] = acc;
    }
    __syncwarp();
    if (j == 0) {
        float mx = sl[0];
        for (int i = 1; i < NCLS; i++) mx = fmaxf(mx, sl[i]);
        float ssum = 0.f;
        for (int i = 0; i < NCLS; i++) ssum += expf(sl[i] - mx);
        sl[10] = mx + logf(ssum);
    }
    __syncwarp();
    if (j < NCLS) out[g * NCLS + j] = sl[j] - sl[10];
}

// ---------------- launch ----------------
extern "C" void kernel_launch(void* const* d_in, const int* in_sizes, int n_in,
                              void* d_out, int out_size)
{
    const float* x    = (const float*)d_in[0];
    const int*   ei   = (const int*)d_in[1];
    const int*   batch= (const int*)d_in[2];
    const float* Wq   = (const float*)d_in[3];
    const float* bq   = (const float*)d_in[4];
    const float* Wk   = (const float*)d_in[5];
    const float* bk   = (const float*)d_in[6];
    const float* Wv   = (const float*)d_in[7];
    const float* bv   = (const float*)d_in[8];
    const float* Ws   = (const float*)d_in[9];
    const float* bs   = (const float*)d_in[10];
    const float* W_fc = (const float*)d_in[11];
    const float* b_fc = (const float*)d_in[12];
    float* out = (float*)d_out;

    const int* src = ei;
    const int* dst = ei + EE;

    const int gemm_gx   = (NN + 127) / 128;          // 391
    const int edge_gx   = (EE * 32 + 255) / 256;     // 75000
    const int edge1_gx  = (EE + 255) / 256;          // 2344
    const int node_gx   = (NN + 255) / 256;          // 196
    const int pool_gx   = (NN * 32 + 255) / 256;     // 6250
    const int prep_gx   = (DD * NCAT + 255) / 256;   // 256

    init_pool_kernel<<<(GG * CC + 255) / 256, 256>>>();

    for (int l = 0; l < 2; l++) {
        init_nodes_kernel<<<node_gx, 256>>>();
        prep_w_kernel<<<prep_gx, 256>>>(
            Wq + l * DD * CC, Wk + l * DD * CC, Wv + l * DD * CC, Ws + l * DD * CC,
            bq + l * CC, bk + l * CC, bv + l * CC, bs + l * CC);
        gemm_wmma_kernel<<<dim3(gemm_gx, 4), 256>>>((l == 0) ? x : nullptr, l);
        edge_score_kernel<<<edge_gx, 256>>>(src, dst);
        edge_exp_kernel<<<edge1_gx, 256>>>(dst);
        edge_scatter_kernel<<<edge_gx, 256>>>(src, dst, l);
    }

    pool_kernel<<<pool_gx, 256>>>(batch);
    final_kernel<<<GG, 32>>>(W_fc, b_fc, out);
}

// round 5
// speedup vs baseline: 1.6913x; 1.2759x over previous
#include <cuda_runtime.h>
#include <math.h>
#include <stdint.h>
#include <mma.h>

using namespace nvcuda;

#define NN     50000
#define NN_PAD 50048          // 391 * 128, so every GEMM CTA stores unguarded
#define EE     600000
#define DD     128
#define CC     128
#define GG     64
#define NCLS   10
#define NCAT   512

// ---------------- scratch (static device globals; no allocation) ----------------
__device__ __align__(16) float g_q[NN_PAD * CC];
__device__ __align__(16) float g_k[NN_PAD * CC];
__device__ __align__(16) float g_v[NN_PAD * CC];
__device__ __align__(16) float g_h0[NN_PAD * CC];   // layer-0 output (pre-relu)
__device__ __align__(16) float g_h1[NN_PAD * CC];   // layer-1 output (pre-relu)
__device__ __align__(16) float g_wh[DD * NCAT];     // tf32-rounded [Wq|Wk|Wv|Ws]
__device__ __align__(16) float g_bcat[NCAT];
// CSR (rebuilt every call)
__device__ int g_deg[NN];
__device__ int g_rowptr[NN + 1];
__device__ int g_wpos[NN];
__device__ int g_srcs[EE];
// pooling
__device__ __align__(16) float g_sums[GG * CC];
__device__ float g_cnt[GG];

// ---------------- helpers ----------------
__device__ __forceinline__ void red_add_v4(float* addr, float a, float b, float c, float d) {
    asm volatile("red.global.add.v4.f32 [%0], {%1, %2, %3, %4};"
                 :: "l"(addr), "f"(a), "f"(b), "f"(c), "f"(d) : "memory");
}

// ---------------- init kernels ----------------
__global__ void init_pool_kernel() {
    int i = blockIdx.x * blockDim.x + threadIdx.x;
    if (i < GG * CC) g_sums[i] = 0.0f;
    if (i < GG) g_cnt[i] = 0.0f;
}

// ---------------- CSR build ----------------
__global__ void csr_zero_kernel() {
    int i = blockIdx.x * blockDim.x + threadIdx.x;
    if (i < NN) g_deg[i] = 0;
}

__global__ void csr_hist_kernel(const int* __restrict__ dst) {
    int e = blockIdx.x * blockDim.x + threadIdx.x;
    if (e < EE) atomicAdd(&g_deg[dst[e]], 1);
}

// single block, 1024 threads: exclusive scan of g_deg -> g_rowptr (+ g_wpos copy)
__global__ void csr_scan_kernel() {
    __shared__ int ssum[1024];
    const int t = threadIdx.x;
    const int CH = (NN + 1023) / 1024;     // 49
    int start = t * CH;
    int end = min(start + CH, NN);
    int s = 0;
    for (int i = start; i < end; i++) s += g_deg[i];
    ssum[t] = s;
    __syncthreads();
    #pragma unroll
    for (int off = 1; off < 1024; off <<= 1) {
        int v = (t >= off) ? ssum[t - off] : 0;
        __syncthreads();
        ssum[t] += v;
        __syncthreads();
    }
    int run = ssum[t] - s;                 // exclusive prefix
    for (int i = start; i < end; i++) {
        g_rowptr[i] = run;
        g_wpos[i]   = run;
        run += g_deg[i];
    }
    if (t == 1023) g_rowptr[NN] = EE;
}

__global__ void csr_scatter_kernel(const int* __restrict__ src, const int* __restrict__ dst) {
    int e = blockIdx.x * blockDim.x + threadIdx.x;
    if (e >= EE) return;
    int pos = atomicAdd(&g_wpos[dst[e]], 1);
    g_srcs[pos] = src[e];
}

// ---------------- weight prep: concat + tf32 round ----------------
__global__ void prep_w_kernel(const float* __restrict__ Wq, const float* __restrict__ Wk,
                              const float* __restrict__ Wv, const float* __restrict__ Ws,
                              const float* __restrict__ bq, const float* __restrict__ bk,
                              const float* __restrict__ bv, const float* __restrict__ bs)
{
    int i = blockIdx.x * 256 + threadIdx.x;
    if (i < DD * NCAT) {
        int k = i >> 9, nc = i & (NCAT - 1);
        int o = nc >> 7, n = nc & 127;
        const float* W = (o == 0) ? Wq : (o == 1) ? Wk : (o == 2) ? Wv : Ws;
        g_wh[i] = wmma::__float_to_tf32(W[k * CC + n]);
    }
    if (i < NCAT) {
        int o = i >> 7, n = i & 127;
        const float* B = (o == 0) ? bq : (o == 1) ? bk : (o == 2) ? bv : bs;
        g_bcat[i] = B[n];
    }
}

// ---------------- wmma tf32 GEMM: Y[:, o*128:+128] = act(X) @ W + b ----------------
__global__ __launch_bounds__(256, 2) void gemm_wmma_kernel(
    const float* __restrict__ X,   // null => relu(g_h0)
    int layer)
{
    __shared__ float sA[128 * 36];
    __shared__ float sB[32 * 132];
    __shared__ float sBias[16 * 132];

    const int tid = threadIdx.x;
    const int w   = tid >> 5;
    const int wr  = w >> 1;
    const int wc  = w & 1;
    const int o   = blockIdx.y;
    const int row0 = blockIdx.x * 128;
    const bool relu = (X == nullptr);
    const float* Xp = relu ? g_h0 : X;

    float* O = (o == 0) ? g_q : (o == 1) ? g_k : (o == 2) ? g_v
             : ((layer == 0) ? g_h0 : g_h1);

    for (int i = tid; i < 16 * 128; i += 256) {
        int r = i >> 7, c = i & 127;
        sBias[r * 132 + c] = g_bcat[o * 128 + c];
    }
    __syncthreads();

    wmma::fragment<wmma::accumulator, 16, 16, 8, float> acc[2][4];
    #pragma unroll
    for (int i = 0; i < 2; i++)
        #pragma unroll
        for (int j = 0; j < 4; j++)
            wmma::load_matrix_sync(acc[i][j], &sBias[wc * 64 + j * 16], 132, wmma::mem_row_major);

    for (int k0 = 0; k0 < DD; k0 += 32) {
        __syncthreads();
        #pragma unroll
        for (int i = tid; i < 1024; i += 256) {
            int r = i >> 3, c4 = i & 7;
            float4 v = make_float4(0.f, 0.f, 0.f, 0.f);
            if (row0 + r < NN)
                v = reinterpret_cast<const float4*>(Xp)[(size_t)(row0 + r) * 32 + (k0 >> 2) + c4];
            if (relu) {
                v.x = fmaxf(v.x, 0.f); v.y = fmaxf(v.y, 0.f);
                v.z = fmaxf(v.z, 0.f); v.w = fmaxf(v.w, 0.f);
            }
            v.x = wmma::__float_to_tf32(v.x);
            v.y = wmma::__float_to_tf32(v.y);
            v.z = wmma::__float_to_tf32(v.z);
            v.w = wmma::__float_to_tf32(v.w);
            *reinterpret_cast<float4*>(&sA[r * 36 + c4 * 4]) = v;
        }
        #pragma unroll
        for (int i = tid; i < 1024; i += 256) {
            int r = i >> 5, c4 = i & 31;
            *reinterpret_cast<float4*>(&sB[r * 132 + c4 * 4]) =
                *reinterpret_cast<const float4*>(&g_wh[(size_t)(k0 + r) * NCAT + o * 128 + c4 * 4]);
        }
        __syncthreads();

        #pragma unroll
        for (int kk = 0; kk < 32; kk += 8) {
            wmma::fragment<wmma::matrix_b, 16, 16, 8, wmma::precision::tf32, wmma::row_major> bf[4];
            #pragma unroll
            for (int j = 0; j < 4; j++)
                wmma::load_matrix_sync(bf[j], &sB[kk * 132 + wc * 64 + j * 16], 132);
            #pragma unroll
            for (int i = 0; i < 2; i++) {
                wmma::fragment<wmma::matrix_a, 16, 16, 8, wmma::precision::tf32, wmma::row_major> af;
                wmma::load_matrix_sync(af, &sA[(wr * 32 + i * 16) * 36 + kk], 36);
                #pragma unroll
                for (int j = 0; j < 4; j++)
                    wmma::mma_sync(acc[i][j], af, bf[j], acc[i][j]);
            }
        }
    }

    #pragma unroll
    for (int i = 0; i < 2; i++)
        #pragma unroll
        for (int j = 0; j < 4; j++)
            wmma::store_matrix_sync(
                O + (size_t)(row0 + wr * 32 + i * 16) * CC + wc * 64 + j * 16,
                acc[i][j], CC, wmma::mem_row_major);
}

// ---------------- fused attention: warp per dst node, online softmax ----------------
__global__ __launch_bounds__(256) void attn_kernel(int layer)
{
    int t = blockIdx.x * 256 + threadIdx.x;
    int d = t >> 5;
    int lane = t & 31;
    if (d >= NN) return;
    int beg = g_rowptr[d];
    int end = g_rowptr[d + 1];
    if (beg == end) return;          // no incoming edges: output stays = skip

    float4 qa = reinterpret_cast<const float4*>(g_q)[(size_t)d * 32 + lane];

    float m = -INFINITY;
    float den = 0.0f;
    float4 acc = make_float4(0.f, 0.f, 0.f, 0.f);

    for (int e = beg; e < end; e++) {
        int s = g_srcs[e];
        float4 ka = reinterpret_cast<const float4*>(g_k)[(size_t)s * 32 + lane];
        float4 va = reinterpret_cast<const float4*>(g_v)[(size_t)s * 32 + lane];
        float dot = qa.x * ka.x + qa.y * ka.y + qa.z * ka.z + qa.w * ka.w;
        #pragma unroll
        for (int o = 16; o > 0; o >>= 1) dot += __shfl_xor_sync(0xffffffffu, dot, o);
        float sc = dot * 0.08838834764831843f;   // 1/sqrt(128)
        float mn = fmaxf(m, sc);
        float corr = __expf(m - mn);             // first iter: exp(-inf)=0
        float w = __expf(sc - mn);
        den = den * corr + w;
        acc.x = acc.x * corr + w * va.x;
        acc.y = acc.y * corr + w * va.y;
        acc.z = acc.z * corr + w * va.z;
        acc.w = acc.w * corr + w * va.w;
        m = mn;
    }

    float inv = 1.0f / den;
    float* O = (layer == 0) ? g_h0 : g_h1;
    float4 o = reinterpret_cast<const float4*>(O)[(size_t)d * 32 + lane];
    o.x += acc.x * inv;
    o.y += acc.y * inv;
    o.z += acc.z * inv;
    o.w += acc.w * inv;
    reinterpret_cast<float4*>(O)[(size_t)d * 32 + lane] = o;
}

// ---------------- global mean pool (reads relu(g_h1)) ----------------
__global__ __launch_bounds__(256) void pool_kernel(const int* __restrict__ batch)
{
    int t = blockIdx.x * 256 + threadIdx.x;
    int n = t >> 5;
    int lane = t & 31;
    if (n >= NN) return;
    int g = batch[n];
    float4 h = reinterpret_cast<const float4*>(g_h1)[(size_t)n * 32 + lane];
    h.x = fmaxf(h.x, 0.f); h.y = fmaxf(h.y, 0.f);
    h.z = fmaxf(h.z, 0.f); h.w = fmaxf(h.w, 0.f);
    red_add_v4(&g_sums[g * CC + lane * 4], h.x, h.y, h.z, h.w);
    if (lane == 0) atomicAdd(&g_cnt[g], 1.0f);
}

// ---------------- classifier + log_softmax ----------------
__global__ void final_kernel(const float* __restrict__ W_fc,
                             const float* __restrict__ b_fc,
                             float* __restrict__ out)
{
    int g = blockIdx.x;
    int j = threadIdx.x;
    __shared__ float sl[12];
    float inv = 1.0f / fmaxf(g_cnt[g], 1.0f);
    if (j < NCLS) {
        float acc = b_fc[j];
        for (int c = 0; c < CC; c++)
            acc += g_sums[g * CC + c] * inv * W_fc[c * NCLS + j];
        sl[j] = acc;
    }
    __syncwarp();
    if (j == 0) {
        float mx = sl[0];
        for (int i = 1; i < NCLS; i++) mx = fmaxf(mx, sl[i]);
        float ssum = 0.f;
        for (int i = 0; i < NCLS; i++) ssum += expf(sl[i] - mx);
        sl[10] = mx + logf(ssum);
    }
    __syncwarp();
    if (j < NCLS) out[g * NCLS + j] = sl[j] - sl[10];
}

// ---------------- launch ----------------
extern "C" void kernel_launch(void* const* d_in, const int* in_sizes, int n_in,
                              void* d_out, int out_size)
{
    const float* x    = (const float*)d_in[0];
    const int*   ei   = (const int*)d_in[1];
    const int*   batch= (const int*)d_in[2];
    const float* Wq   = (const float*)d_in[3];
    const float* bq   = (const float*)d_in[4];
    const float* Wk   = (const float*)d_in[5];
    const float* bk   = (const float*)d_in[6];
    const float* Wv   = (const float*)d_in[7];
    const float* bv   = (const float*)d_in[8];
    const float* Ws   = (const float*)d_in[9];
    const float* bs   = (const float*)d_in[10];
    const float* W_fc = (const float*)d_in[11];
    const float* b_fc = (const float*)d_in[12];
    float* out = (float*)d_out;

    const int* src = ei;
    const int* dst = ei + EE;

    const int gemm_gx  = (NN + 127) / 128;          // 391
    const int node_gx  = (NN + 255) / 256;          // 196
    const int edge_gx  = (EE + 255) / 256;          // 2344
    const int warp_gx  = (NN * 32 + 255) / 256;     // 6250
    const int prep_gx  = (DD * NCAT + 255) / 256;   // 256

    init_pool_kernel<<<(GG * CC + 255) / 256, 256>>>();

    // build CSR (by dst) once per call
    csr_zero_kernel<<<node_gx, 256>>>();
    csr_hist_kernel<<<edge_gx, 256>>>(dst);
    csr_scan_kernel<<<1, 1024>>>();
    csr_scatter_kernel<<<edge_gx, 256>>>(src, dst);

    for (int l = 0; l < 2; l++) {
        prep_w_kernel<<<prep_gx, 256>>>(
            Wq + l * DD * CC, Wk + l * DD * CC, Wv + l * DD * CC, Ws + l * DD * CC,
            bq + l * CC, bk + l * CC, bv + l * CC, bs + l * CC);
        gemm_wmma_kernel<<<dim3(gemm_gx, 4), 256>>>((l == 0) ? x : nullptr, l);
        attn_kernel<<<warp_gx, 256>>>(l);
    }

    pool_kernel<<<warp_gx, 256>>>(batch);
    final_kernel<<<GG, 32>>>(W_fc, b_fc, out);
}

// round 6
// speedup vs baseline: 1.9772x; 1.1691x over previous
#include <cuda_runtime.h>
#include <math.h>
#include <stdint.h>
#include <mma.h>

using namespace nvcuda;

#define NN     50000
#define NN_PAD 50048          // 391 * 128, so every GEMM CTA stores unguarded
#define EE     600000
#define DD     128
#define CC     128
#define GG     64
#define NCLS   10
#define NCAT   512
#define SCAN_BLKS 196         // ceil(NN/256)

// ---------------- scratch (static device globals; no allocation) ----------------
__device__ __align__(16) float g_q[NN_PAD * CC];
__device__ __align__(16) float g_k[NN_PAD * CC];
__device__ __align__(16) float g_v[NN_PAD * CC];
__device__ __align__(16) float g_h0[NN_PAD * CC];   // layer-0 output (pre-relu)
__device__ __align__(16) float g_h1[NN_PAD * CC];   // layer-1 output (pre-relu)
__device__ __align__(16) float g_wh[2 * DD * NCAT]; // tf32-rounded [Wq|Wk|Wv|Ws] per layer
__device__ __align__(16) float g_bcat[2 * NCAT];
// CSR (rebuilt every call)
__device__ int g_deg[SCAN_BLKS * 256];
__device__ int g_rowptr[NN + 1];
__device__ int g_wpos[NN];
__device__ int g_srcs[EE];
__device__ int g_bsum[SCAN_BLKS];
__device__ int g_boff[SCAN_BLKS];
// pooling
__device__ __align__(16) float g_sums[GG * CC];
__device__ float g_cnt[GG];

// ---------------- helpers ----------------
__device__ __forceinline__ void red_add_v4(float* addr, float a, float b, float c, float d) {
    asm volatile("red.global.add.v4.f32 [%0], {%1, %2, %3, %4};"
                 :: "l"(addr), "f"(a), "f"(b), "f"(c), "f"(d) : "memory");
}

// ---------------- init kernels ----------------
__global__ void init_pool_kernel() {
    int i = blockIdx.x * blockDim.x + threadIdx.x;
    if (i < GG * CC) g_sums[i] = 0.0f;
    if (i < GG) g_cnt[i] = 0.0f;
    if (i < SCAN_BLKS * 256) g_deg[i] = 0;   // covers NN with padding zeros
}

// ---------------- CSR build ----------------
__global__ void csr_hist_kernel(const int* __restrict__ dst) {
    int e = blockIdx.x * blockDim.x + threadIdx.x;
    if (e < EE) atomicAdd(&g_deg[dst[e]], 1);
}

// stage 1: per-block sums of 256 deg entries
__global__ void scan_partial_kernel() {
    __shared__ int s[256];
    int i = blockIdx.x * 256 + threadIdx.x;
    int v = g_deg[i];
    s[threadIdx.x] = v;
    __syncthreads();
    #pragma unroll
    for (int off = 128; off > 0; off >>= 1) {
        if (threadIdx.x < off) s[threadIdx.x] += s[threadIdx.x + off];
        __syncthreads();
    }
    if (threadIdx.x == 0) g_bsum[blockIdx.x] = s[0];
}

// stage 2: one block scans SCAN_BLKS partial sums (exclusive)
__global__ void scan_top_kernel() {
    __shared__ int s[256];
    int t = threadIdx.x;
    int v = (t < SCAN_BLKS) ? g_bsum[t] : 0;
    s[t] = v;
    __syncthreads();
    #pragma unroll
    for (int off = 1; off < 256; off <<= 1) {
        int u = (t >= off) ? s[t - off] : 0;
        __syncthreads();
        s[t] += u;
        __syncthreads();
    }
    if (t < SCAN_BLKS) g_boff[t] = s[t] - v;   // exclusive
}

// stage 3: per-block exclusive scan + global offset -> rowptr/wpos
__global__ void scan_final_kernel() {
    __shared__ int s[256];
    int t = threadIdx.x;
    int i = blockIdx.x * 256 + t;
    int v = g_deg[i];
    s[t] = v;
    __syncthreads();
    #pragma unroll
    for (int off = 1; off < 256; off <<= 1) {
        int u = (t >= off) ? s[t - off] : 0;
        __syncthreads();
        s[t] += u;
        __syncthreads();
    }
    int excl = s[t] - v + g_boff[blockIdx.x];
    if (i < NN) {
        g_rowptr[i] = excl;
        g_wpos[i]   = excl;
    }
    if (i == NN - 1 || (blockIdx.x == SCAN_BLKS - 1 && t == 255))
        g_rowptr[NN] = EE;
}

__global__ void csr_scatter_kernel(const int* __restrict__ src, const int* __restrict__ dst) {
    int e = blockIdx.x * blockDim.x + threadIdx.x;
    if (e >= EE) return;
    int pos = atomicAdd(&g_wpos[dst[e]], 1);
    g_srcs[pos] = src[e];
}

// ---------------- weight prep: both layers, concat + tf32 round ----------------
__global__ void prep_w_kernel(const float* __restrict__ Wq, const float* __restrict__ Wk,
                              const float* __restrict__ Wv, const float* __restrict__ Ws,
                              const float* __restrict__ bq, const float* __restrict__ bk,
                              const float* __restrict__ bv, const float* __restrict__ bs)
{
    int l = blockIdx.y;
    int i = blockIdx.x * 256 + threadIdx.x;
    if (i < DD * NCAT) {
        int k = i >> 9, nc = i & (NCAT - 1);
        int o = nc >> 7, n = nc & 127;
        const float* W = (o == 0) ? Wq : (o == 1) ? Wk : (o == 2) ? Wv : Ws;
        g_wh[l * DD * NCAT + i] = wmma::__float_to_tf32(W[l * DD * CC + k * CC + n]);
    }
    if (i < NCAT) {
        int o = i >> 7, n = i & 127;
        const float* B = (o == 0) ? bq : (o == 1) ? bk : (o == 2) ? bv : bs;
        g_bcat[l * NCAT + i] = B[l * CC + n];
    }
}

// ---------------- wmma tf32 GEMM: Y[:, o*128:+128] = act(X) @ W + b ----------------
__global__ __launch_bounds__(256, 2) void gemm_wmma_kernel(
    const float* __restrict__ X,   // null => relu(g_h0)
    int layer)
{
    __shared__ float sA[128 * 36];
    __shared__ float sB[32 * 132];
    __shared__ float sBias[16 * 132];

    const int tid = threadIdx.x;
    const int w   = tid >> 5;
    const int wr  = w >> 1;
    const int wc  = w & 1;
    const int o   = blockIdx.y;
    const int row0 = blockIdx.x * 128;
    const bool relu = (X == nullptr);
    const float* Xp = relu ? g_h0 : X;
    const float* Wl = g_wh + (size_t)layer * DD * NCAT;

    float* O = (o == 0) ? g_q : (o == 1) ? g_k : (o == 2) ? g_v
             : ((layer == 0) ? g_h0 : g_h1);

    for (int i = tid; i < 16 * 128; i += 256) {
        int r = i >> 7, c = i & 127;
        sBias[r * 132 + c] = g_bcat[layer * NCAT + o * 128 + c];
    }
    __syncthreads();

    wmma::fragment<wmma::accumulator, 16, 16, 8, float> acc[2][4];
    #pragma unroll
    for (int i = 0; i < 2; i++)
        #pragma unroll
        for (int j = 0; j < 4; j++)
            wmma::load_matrix_sync(acc[i][j], &sBias[wc * 64 + j * 16], 132, wmma::mem_row_major);

    for (int k0 = 0; k0 < DD; k0 += 32) {
        __syncthreads();
        #pragma unroll
        for (int i = tid; i < 1024; i += 256) {
            int r = i >> 3, c4 = i & 7;
            float4 v = make_float4(0.f, 0.f, 0.f, 0.f);
            if (row0 + r < NN)
                v = reinterpret_cast<const float4*>(Xp)[(size_t)(row0 + r) * 32 + (k0 >> 2) + c4];
            if (relu) {
                v.x = fmaxf(v.x, 0.f); v.y = fmaxf(v.y, 0.f);
                v.z = fmaxf(v.z, 0.f); v.w = fmaxf(v.w, 0.f);
            }
            v.x = wmma::__float_to_tf32(v.x);
            v.y = wmma::__float_to_tf32(v.y);
            v.z = wmma::__float_to_tf32(v.z);
            v.w = wmma::__float_to_tf32(v.w);
            *reinterpret_cast<float4*>(&sA[r * 36 + c4 * 4]) = v;
        }
        #pragma unroll
        for (int i = tid; i < 1024; i += 256) {
            int r = i >> 5, c4 = i & 31;
            *reinterpret_cast<float4*>(&sB[r * 132 + c4 * 4]) =
                *reinterpret_cast<const float4*>(&Wl[(size_t)(k0 + r) * NCAT + o * 128 + c4 * 4]);
        }
        __syncthreads();

        #pragma unroll
        for (int kk = 0; kk < 32; kk += 8) {
            wmma::fragment<wmma::matrix_b, 16, 16, 8, wmma::precision::tf32, wmma::row_major> bf[4];
            #pragma unroll
            for (int j = 0; j < 4; j++)
                wmma::load_matrix_sync(bf[j], &sB[kk * 132 + wc * 64 + j * 16], 132);
            #pragma unroll
            for (int i = 0; i < 2; i++) {
                wmma::fragment<wmma::matrix_a, 16, 16, 8, wmma::precision::tf32, wmma::row_major> af;
                wmma::load_matrix_sync(af, &sA[(wr * 32 + i * 16) * 36 + kk], 36);
                #pragma unroll
                for (int j = 0; j < 4; j++)
                    wmma::mma_sync(acc[i][j], af, bf[j], acc[i][j]);
            }
        }
    }

    #pragma unroll
    for (int i = 0; i < 2; i++)
        #pragma unroll
        for (int j = 0; j < 4; j++)
            wmma::store_matrix_sync(
                O + (size_t)(row0 + wr * 32 + i * 16) * CC + wc * 64 + j * 16,
                acc[i][j], CC, wmma::mem_row_major);
}

// ---------------- fused attention: warp per dst node, online softmax ----------------
__global__ __launch_bounds__(256) void attn_kernel(int layer)
{
    int t = blockIdx.x * 256 + threadIdx.x;
    int d = t >> 5;
    int lane = t & 31;
    if (d >= NN) return;
    int beg = g_rowptr[d];
    int end = g_rowptr[d + 1];
    if (beg == end) return;          // no incoming edges: output stays = skip

    float4 qa = reinterpret_cast<const float4*>(g_q)[(size_t)d * 32 + lane];

    float m = -INFINITY;
    float den = 0.0f;
    float4 acc = make_float4(0.f, 0.f, 0.f, 0.f);

    for (int e = beg; e < end; e++) {
        int s = g_srcs[e];
        float4 ka = reinterpret_cast<const float4*>(g_k)[(size_t)s * 32 + lane];
        float4 va = reinterpret_cast<const float4*>(g_v)[(size_t)s * 32 + lane];
        float dot = qa.x * ka.x + qa.y * ka.y + qa.z * ka.z + qa.w * ka.w;
        #pragma unroll
        for (int o = 16; o > 0; o >>= 1) dot += __shfl_xor_sync(0xffffffffu, dot, o);
        float sc = dot * 0.08838834764831843f;   // 1/sqrt(128)
        float mn = fmaxf(m, sc);
        float corr = __expf(m - mn);             // first iter: exp(-inf)=0
        float w = __expf(sc - mn);
        den = den * corr + w;
        acc.x = acc.x * corr + w * va.x;
        acc.y = acc.y * corr + w * va.y;
        acc.z = acc.z * corr + w * va.z;
        acc.w = acc.w * corr + w * va.w;
        m = mn;
    }

    float inv = 1.0f / den;
    float* O = (layer == 0) ? g_h0 : g_h1;
    float4 o = reinterpret_cast<const float4*>(O)[(size_t)d * 32 + lane];
    o.x += acc.x * inv;
    o.y += acc.y * inv;
    o.z += acc.z * inv;
    o.w += acc.w * inv;
    reinterpret_cast<float4*>(O)[(size_t)d * 32 + lane] = o;
}

// ---------------- global mean pool (reads relu(g_h1)) ----------------
__global__ __launch_bounds__(256) void pool_kernel(const int* __restrict__ batch)
{
    int t = blockIdx.x * 256 + threadIdx.x;
    int n = t >> 5;
    int lane = t & 31;
    if (n >= NN) return;
    int g = batch[n];
    float4 h = reinterpret_cast<const float4*>(g_h1)[(size_t)n * 32 + lane];
    h.x = fmaxf(h.x, 0.f); h.y = fmaxf(h.y, 0.f);
    h.z = fmaxf(h.z, 0.f); h.w = fmaxf(h.w, 0.f);
    red_add_v4(&g_sums[g * CC + lane * 4], h.x, h.y, h.z, h.w);
    if (lane == 0) atomicAdd(&g_cnt[g], 1.0f);
}

// ---------------- classifier + log_softmax ----------------
__global__ void final_kernel(const float* __restrict__ W_fc,
                             const float* __restrict__ b_fc,
                             float* __restrict__ out)
{
    int g = blockIdx.x;
    int j = threadIdx.x;
    __shared__ float sl[12];
    float inv = 1.0f / fmaxf(g_cnt[g], 1.0f);
    if (j < NCLS) {
        float acc = b_fc[j];
        for (int c = 0; c < CC; c++)
            acc += g_sums[g * CC + c] * inv * W_fc[c * NCLS + j];
        sl[j] = acc;
    }
    __syncwarp();
    if (j == 0) {
        float mx = sl[0];
        for (int i = 1; i < NCLS; i++) mx = fmaxf(mx, sl[i]);
        float ssum = 0.f;
        for (int i = 0; i < NCLS; i++) ssum += expf(sl[i] - mx);
        sl[10] = mx + logf(ssum);
    }
    __syncwarp();
    if (j < NCLS) out[g * NCLS + j] = sl[j] - sl[10];
}

// ---------------- launch ----------------
extern "C" void kernel_launch(void* const* d_in, const int* in_sizes, int n_in,
                              void* d_out, int out_size)
{
    const float* x    = (const float*)d_in[0];
    const int*   ei   = (const int*)d_in[1];
    const int*   batch= (const int*)d_in[2];
    const float* Wq   = (const float*)d_in[3];
    const float* bq   = (const float*)d_in[4];
    const float* Wk   = (const float*)d_in[5];
    const float* bk   = (const float*)d_in[6];
    const float* Wv   = (const float*)d_in[7];
    const float* bv   = (const float*)d_in[8];
    const float* Ws   = (const float*)d_in[9];
    const float* bs   = (const float*)d_in[10];
    const float* W_fc = (const float*)d_in[11];
    const float* b_fc = (const float*)d_in[12];
    float* out = (float*)d_out;

    const int* src = ei;
    const int* dst = ei + EE;

    const int gemm_gx  = (NN + 127) / 128;          // 391
    const int edge_gx  = (EE + 255) / 256;          // 2344
    const int warp_gx  = (NN * 32 + 255) / 256;     // 6250
    const int prep_gx  = (DD * NCAT + 255) / 256;   // 256

    init_pool_kernel<<<SCAN_BLKS, 256>>>();
    prep_w_kernel<<<dim3(prep_gx, 2), 256>>>(Wq, Wk, Wv, Ws, bq, bk, bv, bs);

    // build CSR (by dst) once per call — hierarchical scan
    csr_hist_kernel<<<edge_gx, 256>>>(dst);
    scan_partial_kernel<<<SCAN_BLKS, 256>>>();
    scan_top_kernel<<<1, 256>>>();
    scan_final_kernel<<<SCAN_BLKS, 256>>>();
    csr_scatter_kernel<<<edge_gx, 256>>>(src, dst);

    for (int l = 0; l < 2; l++) {
        gemm_wmma_kernel<<<dim3(gemm_gx, 4), 256>>>((l == 0) ? x : nullptr, l);
        attn_kernel<<<warp_gx, 256>>>(l);
    }

    pool_kernel<<<warp_gx, 256>>>(batch);
    final_kernel<<<GG, 32>>>(W_fc, b_fc, out);
}